// round 1
// baseline (speedup 1.0000x reference)
#include <cuda_runtime.h>
#include <cstdint>
#include <cstddef>

// Problem constants
#define T_ 1024
#define B_ 128
#define IN_ 256
#define H_ 512

// ---------------- scratch (device globals: allocation-free rule) ----------------
__device__ float g_proj[(size_t)2 * T_ * B_ * H_];   // 512 MiB, reused for proj0 then proj1
__device__ float g_S[(size_t)T_ * B_ * (2 * H_)];    // 512 MiB, layer0 states [t][b][1024]
__device__ float g_hbuf[2][2][B_][H_];               // ping-pong recurrent state
__device__ float g_out1[B_ * (2 * H_)];
__device__ float g_z1[B_ * (2 * H_)];
__device__ float g_h1[B_ * (4 * H_)];
__device__ float g_z2[B_ * (4 * H_)];
__device__ unsigned long long g_tick[2];             // monotonic barrier tickets (replay-safe)

// ---------------- grid barrier (persistent scan) ----------------
// Monotonic ticket barrier: never reset, so it is safe across the correctness
// run, graph capture, and every graph replay. One counter per direction.
__device__ __forceinline__ void gbar(int which, unsigned nct) {
    __syncthreads();
    if (threadIdx.x == 0) {
        __threadfence();
        unsigned long long t = atomicAdd(&g_tick[which], 1ULL);
        unsigned long long target = (t / nct + 1ULL) * (unsigned long long)nct;
        while (__ldcg(&g_tick[which]) < target) __nanosleep(64);
        __threadfence();
    }
    __syncthreads();
}

// ---------------- generic fp32 GEMM: C[m,n] = sum_k A[m,k] * W[n,k] (+bias, act) ----------------
// BM=BN=64, BK=16, 256 threads, 4x4 micro-tile, double-buffered smem, reg prefetch.
#define OM_PLAIN 0
#define OM_PROJ0 1   // row r = b*T + t  (A = x [B,T,IN]) -> out [d][t][b][h]
#define OM_PROJ1 2   // row r = t*B + b  (A = S [T*B,1024]) -> out [d][t][b][h]
#define ACT_NONE 0
#define ACT_SIGMOID 1

__global__ void __launch_bounds__(256) gemm_atb(
    const float* __restrict__ A, int lda,
    const float* __restrict__ W, int ldw,
    const float* __restrict__ bias1, const float* __restrict__ bias2,
    float* __restrict__ C, int M, int N, int K,
    int out_mode, int act)
{
    __shared__ float a_sm[2][16][68];
    __shared__ float w_sm[2][16][68];
    const int tid = threadIdx.x;
    const int row0 = blockIdx.y * 64;
    const int col0 = blockIdx.x * 64;
    const int lm = tid >> 2;          // 0..63
    const int lk = (tid & 3) << 2;    // 0,4,8,12

    const float* Ap = A + (size_t)(row0 + lm) * lda + lk;
    const float* Wp = W + (size_t)(col0 + lm) * ldw + lk;
    const int nkt = K >> 4;

    float4 af = *(const float4*)Ap;
    float4 wf = *(const float4*)Wp;
    a_sm[0][lk + 0][lm] = af.x; a_sm[0][lk + 1][lm] = af.y;
    a_sm[0][lk + 2][lm] = af.z; a_sm[0][lk + 3][lm] = af.w;
    w_sm[0][lk + 0][lm] = wf.x; w_sm[0][lk + 1][lm] = wf.y;
    w_sm[0][lk + 2][lm] = wf.z; w_sm[0][lk + 3][lm] = wf.w;
    __syncthreads();

    const int tx = tid & 15, ty = tid >> 4;
    float acc[4][4];
#pragma unroll
    for (int i = 0; i < 4; i++)
#pragma unroll
        for (int j = 0; j < 4; j++) acc[i][j] = 0.f;

    for (int kt = 0; kt < nkt; kt++) {
        const int buf = kt & 1;
        if (kt + 1 < nkt) {
            af = *(const float4*)(Ap + (size_t)(kt + 1) * 16);
            wf = *(const float4*)(Wp + (size_t)(kt + 1) * 16);
        }
#pragma unroll
        for (int k = 0; k < 16; k++) {
            float4 av = *(const float4*)&a_sm[buf][k][ty << 2];
            float4 wv = *(const float4*)&w_sm[buf][k][tx << 2];
            acc[0][0] = fmaf(av.x, wv.x, acc[0][0]);
            acc[0][1] = fmaf(av.x, wv.y, acc[0][1]);
            acc[0][2] = fmaf(av.x, wv.z, acc[0][2]);
            acc[0][3] = fmaf(av.x, wv.w, acc[0][3]);
            acc[1][0] = fmaf(av.y, wv.x, acc[1][0]);
            acc[1][1] = fmaf(av.y, wv.y, acc[1][1]);
            acc[1][2] = fmaf(av.y, wv.z, acc[1][2]);
            acc[1][3] = fmaf(av.y, wv.w, acc[1][3]);
            acc[2][0] = fmaf(av.z, wv.x, acc[2][0]);
            acc[2][1] = fmaf(av.z, wv.y, acc[2][1]);
            acc[2][2] = fmaf(av.z, wv.z, acc[2][2]);
            acc[2][3] = fmaf(av.z, wv.w, acc[2][3]);
            acc[3][0] = fmaf(av.w, wv.x, acc[3][0]);
            acc[3][1] = fmaf(av.w, wv.y, acc[3][1]);
            acc[3][2] = fmaf(av.w, wv.z, acc[3][2]);
            acc[3][3] = fmaf(av.w, wv.w, acc[3][3]);
        }
        if (kt + 1 < nkt) {
            const int nb = buf ^ 1;
            a_sm[nb][lk + 0][lm] = af.x; a_sm[nb][lk + 1][lm] = af.y;
            a_sm[nb][lk + 2][lm] = af.z; a_sm[nb][lk + 3][lm] = af.w;
            w_sm[nb][lk + 0][lm] = wf.x; w_sm[nb][lk + 1][lm] = wf.y;
            w_sm[nb][lk + 2][lm] = wf.z; w_sm[nb][lk + 3][lm] = wf.w;
        }
        __syncthreads();
    }

    // epilogue
    float bj[4];
#pragma unroll
    for (int j = 0; j < 4; j++) {
        const int n = col0 + (tx << 2) + j;
        float b = 0.f;
        if (bias1) b += bias1[n];
        if (bias2) b += bias2[n];
        bj[j] = b;
    }
#pragma unroll
    for (int i = 0; i < 4; i++) {
#pragma unroll
        for (int j = 0; j < 4; j++) {
            const int m = row0 + (ty << 2) + i;
            const int n = col0 + (tx << 2) + j;
            float v = acc[i][j] + bj[j];
            if (act == ACT_SIGMOID) v = 1.f / (1.f + expf(-v));
            size_t idx;
            if (out_mode == OM_PLAIN) {
                idx = (size_t)m * N + n;
            } else {
                int tt, bb;
                if (out_mode == OM_PROJ0) { bb = m >> 10; tt = m & 1023; }
                else                      { tt = m >> 7;  bb = m & 127;  }
                idx = (((size_t)(n >> 9) * T_ + tt) * B_ + bb) * H_ + (n & 511);
            }
            C[idx] = v;
        }
    }
}

// ---------------- persistent recurrent scan ----------------
// 128 CTAs (2 dirs x 4 b-tiles x 16 h-tiles), 256 threads. Each CTA keeps its
// 32-col slice of W_hh^T resident in smem (64 KB) for all 1024 steps.
// h state ping-pongs in g_hbuf (L2-resident); cross-CTA reads use __ldcg.
#define SCAN_SMEM ((512 * 32 + 2 * 32 * 64) * 4)   // 81920 B

__global__ void __launch_bounds__(256) scan_kernel(
    const float* __restrict__ proj,   // [2][T][B][H]
    const float* __restrict__ Whh,    // [2][H][H]
    const float* __restrict__ hinit,  // [2][B][H]
    float* __restrict__ S,            // [T][B][2H] or null
    float* __restrict__ outF)         // [B][2H] or null
{
    extern __shared__ float sm[];
    float* wt = sm;                   // [512][32] (transposed W slice)
    float* ash = sm + 512 * 32;       // [2][32][64] h-chunk double buffer

    const int tid = threadIdx.x;
    const int cta = blockIdx.x;
    const int d = cta >> 6;
    const int rem = cta & 63;
    const int b0 = (rem >> 4) << 5;
    const int n0 = (rem & 15) << 5;

    // Load W_hh[d][n0:n0+32][:] transposed into smem (once).
    {
        const int n = tid >> 3;            // 0..31
        const int kq = (tid & 7) << 2;     // 0..28
        const float* wp = Whh + ((size_t)d * H_ + n0 + n) * H_;
        for (int kb = 0; kb < H_; kb += 32) {
            float4 v = *(const float4*)(wp + kb + kq);
            const int k = kb + kq;
            wt[(k + 0) * 32 + n] = v.x;
            wt[(k + 1) * 32 + n] = v.y;
            wt[(k + 2) * 32 + n] = v.z;
            wt[(k + 3) * 32 + n] = v.w;
        }
    }
    // Init h state (parity 0) with this CTA's tile of hinit.
    for (int i = tid; i < 1024; i += 256) {
        const int m = i >> 5, nn = i & 31;
        g_hbuf[0][d][b0 + m][n0 + nn] = hinit[((size_t)d * B_ + b0 + m) * H_ + n0 + nn];
    }
    gbar(d, 64);

    const int tx = tid & 15, ty = tid >> 4;
    const int m0 = ty << 1;            // 2 rows per thread
    const int nn0 = tx << 1;           // 2 cols per thread
    const int am = tid >> 3;           // loader row 0..31
    const int ak = (tid & 7) << 3;     // loader k offset 0..56

    for (int t = 0; t < T_; t++) {
        const float* hp = &g_hbuf[t & 1][d][0][0];
        float* hn = &g_hbuf[(t + 1) & 1][d][0][0];
        const float* pp = proj + (((size_t)d * T_ + t) * B_) * H_;

        // prefetch the 4 projection values for this thread's micro-tile
        const size_t pr0 = (size_t)(b0 + m0) * H_ + n0 + nn0;
        const size_t pr1 = (size_t)(b0 + m0 + 1) * H_ + n0 + nn0;
        const float p00 = pp[pr0], p01 = pp[pr0 + 1];
        const float p10 = pp[pr1], p11 = pp[pr1 + 1];

        const float* arow = hp + (size_t)(b0 + am) * H_ + ak;
        float4 f0 = __ldcg((const float4*)(arow));
        float4 f1 = __ldcg((const float4*)(arow + 4));
        *(float4*)&ash[am * 64 + ak] = f0;
        *(float4*)&ash[am * 64 + ak + 4] = f1;
        __syncthreads();

        float acc00 = 0.f, acc01 = 0.f, acc10 = 0.f, acc11 = 0.f;
        for (int c = 0; c < 8; c++) {
            if (c < 7) {
                f0 = __ldcg((const float4*)(arow + (c + 1) * 64));
                f1 = __ldcg((const float4*)(arow + (c + 1) * 64 + 4));
            }
            const float* ac = ash + (c & 1) * 2048;
            const float* wr = wt + (size_t)(c << 6) * 32;
#pragma unroll
            for (int k = 0; k < 64; k++) {
                const float a0v = ac[m0 * 64 + k];
                const float a1v = ac[(m0 + 1) * 64 + k];
                const float2 wv = *(const float2*)(wr + k * 32 + nn0);
                acc00 = fmaf(a0v, wv.x, acc00);
                acc01 = fmaf(a0v, wv.y, acc01);
                acc10 = fmaf(a1v, wv.x, acc10);
                acc11 = fmaf(a1v, wv.y, acc11);
            }
            if (c < 7) {
                float* ab = ash + ((c + 1) & 1) * 2048;
                *(float4*)&ab[am * 64 + ak] = f0;
                *(float4*)&ab[am * 64 + ak + 4] = f1;
            }
            __syncthreads();
        }

        const float v00 = fmaxf(acc00 + p00, 0.f);
        const float v01 = fmaxf(acc01 + p01, 0.f);
        const float v10 = fmaxf(acc10 + p10, 0.f);
        const float v11 = fmaxf(acc11 + p11, 0.f);

        hn[pr0] = v00; hn[pr0 + 1] = v01;
        hn[pr1] = v10; hn[pr1 + 1] = v11;
        if (S) {
            const size_t s0 = ((size_t)t * B_ + b0 + m0) * (2 * H_) + ((size_t)d << 9) + n0 + nn0;
            S[s0] = v00; S[s0 + 1] = v01;
            S[s0 + 2 * H_] = v10; S[s0 + 2 * H_ + 1] = v11;
        }
        if (outF && t == T_ - 1) {
            const size_t o0 = (size_t)(b0 + m0) * (2 * H_) + ((size_t)d << 9) + n0 + nn0;
            outF[o0] = v00; outF[o0 + 1] = v01;
            outF[o0 + 2 * H_] = v10; outF[o0 + 2 * H_ + 1] = v11;
        }
        gbar(d, 64);
    }
}

// ---------------- BatchNorm(train, biased var) + ReLU ----------------
__global__ void bn_relu(const float* __restrict__ in, float* __restrict__ out,
                        const float* __restrict__ gamma, const float* __restrict__ beta,
                        int Nf)
{
    const int n = blockIdx.x;
    const int t = threadIdx.x;   // 128 = batch
    const float v = in[(size_t)t * Nf + n];
    __shared__ float red[128];
    red[t] = v;
    __syncthreads();
    for (int s = 64; s > 0; s >>= 1) { if (t < s) red[t] += red[t + s]; __syncthreads(); }
    const float mean = red[0] * (1.f / 128.f);
    __syncthreads();
    const float dv = v - mean;
    red[t] = dv * dv;
    __syncthreads();
    for (int s = 64; s > 0; s >>= 1) { if (t < s) red[t] += red[t + s]; __syncthreads(); }
    const float var = red[0] * (1.f / 128.f);
    const float z = dv * rsqrtf(var + 1e-5f) * gamma[n] + beta[n];
    out[(size_t)t * Nf + n] = fmaxf(z, 0.f);
}

// ---------------- launch ----------------
extern "C" void kernel_launch(void* const* d_in, const int* in_sizes, int n_in,
                              void* d_out, int out_size)
{
    (void)in_sizes; (void)n_in; (void)out_size;
    const float* x     = (const float*)d_in[0];
    const float* h0    = (const float*)d_in[1];
    const float* W_ih0 = (const float*)d_in[2];
    const float* W_hh0 = (const float*)d_in[3];
    const float* b_ih0 = (const float*)d_in[4];
    const float* b_hh0 = (const float*)d_in[5];
    const float* W_ih1 = (const float*)d_in[6];
    const float* W_hh1 = (const float*)d_in[7];
    const float* b_ih1 = (const float*)d_in[8];
    const float* b_hh1 = (const float*)d_in[9];
    const float* bn1_g = (const float*)d_in[10];
    const float* bn1_b = (const float*)d_in[11];
    const float* fc1_W = (const float*)d_in[12];
    const float* fc1_b = (const float*)d_in[13];
    const float* bn2_g = (const float*)d_in[14];
    const float* bn2_b = (const float*)d_in[15];
    const float* fc2_W = (const float*)d_in[16];
    const float* fc2_b = (const float*)d_in[17];
    float* out = (float*)d_out;

    cudaFuncSetAttribute(scan_kernel, cudaFuncAttributeMaxDynamicSharedMemorySize, SCAN_SMEM);

    float *pProj, *pS, *pOut1, *pZ1, *pH1, *pZ2;
    cudaGetSymbolAddress((void**)&pProj, g_proj);
    cudaGetSymbolAddress((void**)&pS, g_S);
    cudaGetSymbolAddress((void**)&pOut1, g_out1);
    cudaGetSymbolAddress((void**)&pZ1, g_z1);
    cudaGetSymbolAddress((void**)&pH1, g_h1);
    cudaGetSymbolAddress((void**)&pZ2, g_z2);

    const int MT = B_ * T_;  // 131072

    // layer0 input projection: [131072,256] x [1024,256]^T -> proj[d][t][b][h]
    gemm_atb<<<dim3((2 * H_) / 64, MT / 64), 256>>>(
        x, IN_, W_ih0, IN_, b_ih0, b_hh0, pProj, MT, 2 * H_, IN_, OM_PROJ0, ACT_NONE);

    // layer0 scan (stores all states into S)
    scan_kernel<<<128, 256, SCAN_SMEM>>>(pProj, W_hh0, h0, pS, nullptr);

    // layer1 input projection: [131072,1024] x [1024,1024]^T -> proj[d][t][b][h]
    gemm_atb<<<dim3((2 * H_) / 64, MT / 64), 256>>>(
        pS, 2 * H_, W_ih1, 2 * H_, b_ih1, b_hh1, pProj, MT, 2 * H_, 2 * H_, OM_PROJ1, ACT_NONE);

    // layer1 scan (only final state needed)
    scan_kernel<<<128, 256, SCAN_SMEM>>>(pProj, W_hh1, h0 + 2 * B_ * H_, nullptr, pOut1);

    // head
    bn_relu<<<2 * H_, 128>>>(pOut1, pZ1, bn1_g, bn1_b, 2 * H_);
    gemm_atb<<<dim3((4 * H_) / 64, B_ / 64), 256>>>(
        pZ1, 2 * H_, fc1_W, 2 * H_, fc1_b, nullptr, pH1, B_, 4 * H_, 2 * H_, OM_PLAIN, ACT_NONE);
    bn_relu<<<4 * H_, 128>>>(pH1, pZ2, bn2_g, bn2_b, 4 * H_);
    gemm_atb<<<dim3(128 / 64, B_ / 64), 256>>>(
        pZ2, 4 * H_, fc2_W, 4 * H_, fc2_b, nullptr, out, B_, 128, 4 * H_, OM_PLAIN, ACT_SIGMOID);
}

// round 3
// speedup vs baseline: 1.2063x; 1.2063x over previous
#include <cuda_runtime.h>
#include <cuda_bf16.h>
#include <cstdint>
#include <cstddef>

// Problem constants
#define T_ 1024
#define B_ 128
#define IN_ 256
#define H_ 512

// ---------------- scratch (device globals: allocation-free rule) ----------------
__device__ float g_proj[(size_t)2 * T_ * B_ * H_];   // reused for proj0 then proj1
__device__ float g_S[(size_t)T_ * B_ * (2 * H_)];    // layer0 states [t][b][1024]
__device__ float g_hbuf[2][2][B_][H_];               // ping-pong recurrent state
__device__ float g_out1[B_ * (2 * H_)];
__device__ float g_z1[B_ * (2 * H_)];
__device__ float g_h1[B_ * (4 * H_)];
__device__ float g_z2[B_ * (4 * H_)];
__device__ unsigned long long g_tick[2];             // monotonic barrier tickets (replay-safe)

// ---------------- grid barrier (persistent scan) ----------------
__device__ __forceinline__ void gbar(int which, unsigned nct) {
    __syncthreads();
    if (threadIdx.x == 0) {
        __threadfence();
        unsigned long long t = atomicAdd(&g_tick[which], 1ULL);
        unsigned long long target = (t / nct + 1ULL) * (unsigned long long)nct;
        while (__ldcg(&g_tick[which]) < target) __nanosleep(64);
        __threadfence();
    }
    __syncthreads();
}

#define OM_PLAIN 0
#define OM_PROJ0 1   // row r = b*T + t  (A = x [B,T,IN]) -> out [d][t][b][h]
#define OM_PROJ1 2   // row r = t*B + b  (A = S [T*B,1024]) -> out [d][t][b][h]
#define ACT_NONE 0
#define ACT_SIGMOID 1

// ==================================================================================
// Tensor-core GEMM (bf16 split-2, fp32 accumulate): C[m,n] = sum_k A[m,k]*W[n,k]
// CTA tile 128x128, 8 warps (2x4) each 64x32, K-chunk 32.
// a = a_hi + a_lo (bf16); C += a_hi*w_hi + a_hi*w_lo + a_lo*w_hi  (~1e-5 rel err)
// ==================================================================================

__device__ __forceinline__ void mma16816(float& c0, float& c1, float& c2, float& c3,
                                         uint32_t a0, uint32_t a1, uint32_t a2, uint32_t a3,
                                         uint32_t b0, uint32_t b1)
{
    asm volatile(
        "mma.sync.aligned.m16n8k16.row.col.f32.bf16.bf16.f32 "
        "{%0,%1,%2,%3}, {%4,%5,%6,%7}, {%8,%9}, {%0,%1,%2,%3};"
        : "+f"(c0), "+f"(c1), "+f"(c2), "+f"(c3)
        : "r"(a0), "r"(a1), "r"(a2), "r"(a3), "r"(b0), "r"(b1));
}

#define SMSTR 40   // bf16 elements per smem row (32 + 8 pad) -> conflict-free frags

__global__ void __launch_bounds__(256) gemm_tc(
    const float* __restrict__ A, int lda,
    const float* __restrict__ W, int ldw,
    const float* __restrict__ bias1, const float* __restrict__ bias2,
    float* __restrict__ C, int K, int out_mode)
{
    __shared__ __nv_bfloat16 sAh[128 * SMSTR];
    __shared__ __nv_bfloat16 sAl[128 * SMSTR];
    __shared__ __nv_bfloat16 sWh[128 * SMSTR];
    __shared__ __nv_bfloat16 sWl[128 * SMSTR];

    const int tid = threadIdx.x;
    const int row0 = blockIdx.y * 128;
    const int col0 = blockIdx.x * 128;

    // loader mapping: 2 threads per row, each covers 16 consecutive k
    const int lrow = tid >> 1;
    const int lcol = (tid & 1) << 4;
    const float* Ap = A + (size_t)(row0 + lrow) * lda + lcol;
    const float* Wp = W + (size_t)(col0 + lrow) * ldw + lcol;

    const int nch = K >> 5;

    float4 apre[4], wpre[4];
#pragma unroll
    for (int j = 0; j < 4; j++) {
        apre[j] = *(const float4*)(Ap + j * 4);
        wpre[j] = *(const float4*)(Wp + j * 4);
    }

    const int warp = tid >> 5;
    const int lane = tid & 31;
    const int wm = warp >> 2;          // 0..1
    const int wn = warp & 3;           // 0..3
    const int g = lane >> 2;           // 0..7
    const int t2 = (lane & 3) << 1;    // 0,2,4,6

    float acc[4][4][4];
#pragma unroll
    for (int mi = 0; mi < 4; mi++)
#pragma unroll
        for (int ni = 0; ni < 4; ni++)
#pragma unroll
            for (int r = 0; r < 4; r++) acc[mi][ni][r] = 0.f;

    for (int c = 0; c < nch; c++) {
        // store prefetched chunk to smem (fp32 -> bf16 hi/lo)
#pragma unroll
        for (int j = 0; j < 4; j++) {
            float4 v = apre[j];
            __nv_bfloat16 hx = __float2bfloat16(v.x);
            __nv_bfloat16 hy = __float2bfloat16(v.y);
            __nv_bfloat16 hz = __float2bfloat16(v.z);
            __nv_bfloat16 hw = __float2bfloat16(v.w);
            __nv_bfloat16 lx = __float2bfloat16(v.x - __bfloat162float(hx));
            __nv_bfloat16 ly = __float2bfloat16(v.y - __bfloat162float(hy));
            __nv_bfloat16 lz = __float2bfloat16(v.z - __bfloat162float(hz));
            __nv_bfloat16 lw = __float2bfloat16(v.w - __bfloat162float(hw));
            const int o = lrow * SMSTR + lcol + j * 4;
            *(__nv_bfloat162*)&sAh[o]     = __halves2bfloat162(hx, hy);
            *(__nv_bfloat162*)&sAh[o + 2] = __halves2bfloat162(hz, hw);
            *(__nv_bfloat162*)&sAl[o]     = __halves2bfloat162(lx, ly);
            *(__nv_bfloat162*)&sAl[o + 2] = __halves2bfloat162(lz, lw);
            v = wpre[j];
            hx = __float2bfloat16(v.x); hy = __float2bfloat16(v.y);
            hz = __float2bfloat16(v.z); hw = __float2bfloat16(v.w);
            lx = __float2bfloat16(v.x - __bfloat162float(hx));
            ly = __float2bfloat16(v.y - __bfloat162float(hy));
            lz = __float2bfloat16(v.z - __bfloat162float(hz));
            lw = __float2bfloat16(v.w - __bfloat162float(hw));
            *(__nv_bfloat162*)&sWh[o]     = __halves2bfloat162(hx, hy);
            *(__nv_bfloat162*)&sWh[o + 2] = __halves2bfloat162(hz, hw);
            *(__nv_bfloat162*)&sWl[o]     = __halves2bfloat162(lx, ly);
            *(__nv_bfloat162*)&sWl[o + 2] = __halves2bfloat162(lz, lw);
        }
        __syncthreads();

        // prefetch next chunk into registers (overlaps with MMA below)
        if (c + 1 < nch) {
#pragma unroll
            for (int j = 0; j < 4; j++) {
                apre[j] = *(const float4*)(Ap + (size_t)(c + 1) * 32 + j * 4);
                wpre[j] = *(const float4*)(Wp + (size_t)(c + 1) * 32 + j * 4);
            }
        }

#pragma unroll
        for (int s = 0; s < 2; s++) {
            const int kb = (s << 4) + t2;
            uint32_t aF[4][4], bH[4][2], bL[4][2];
#pragma unroll
            for (int mi = 0; mi < 4; mi++) {
                const int mb = ((wm << 6) + (mi << 4) + g) * SMSTR + kb;
                aF[mi][0] = *(const uint32_t*)&sAh[mb];
                aF[mi][1] = *(const uint32_t*)&sAh[mb + 8 * SMSTR];
                aF[mi][2] = *(const uint32_t*)&sAh[mb + 8];
                aF[mi][3] = *(const uint32_t*)&sAh[mb + 8 * SMSTR + 8];
            }
#pragma unroll
            for (int ni = 0; ni < 4; ni++) {
                const int nb = ((wn << 5) + (ni << 3) + g) * SMSTR + kb;
                bH[ni][0] = *(const uint32_t*)&sWh[nb];
                bH[ni][1] = *(const uint32_t*)&sWh[nb + 8];
                bL[ni][0] = *(const uint32_t*)&sWl[nb];
                bL[ni][1] = *(const uint32_t*)&sWl[nb + 8];
            }
            // pass 1: a_hi * w_hi ; pass 2: a_hi * w_lo
#pragma unroll
            for (int mi = 0; mi < 4; mi++)
#pragma unroll
                for (int ni = 0; ni < 4; ni++) {
                    mma16816(acc[mi][ni][0], acc[mi][ni][1], acc[mi][ni][2], acc[mi][ni][3],
                             aF[mi][0], aF[mi][1], aF[mi][2], aF[mi][3], bH[ni][0], bH[ni][1]);
                    mma16816(acc[mi][ni][0], acc[mi][ni][1], acc[mi][ni][2], acc[mi][ni][3],
                             aF[mi][0], aF[mi][1], aF[mi][2], aF[mi][3], bL[ni][0], bL[ni][1]);
                }
            // pass 3: a_lo * w_hi
#pragma unroll
            for (int mi = 0; mi < 4; mi++) {
                const int mb = ((wm << 6) + (mi << 4) + g) * SMSTR + kb;
                aF[mi][0] = *(const uint32_t*)&sAl[mb];
                aF[mi][1] = *(const uint32_t*)&sAl[mb + 8 * SMSTR];
                aF[mi][2] = *(const uint32_t*)&sAl[mb + 8];
                aF[mi][3] = *(const uint32_t*)&sAl[mb + 8 * SMSTR + 8];
            }
#pragma unroll
            for (int mi = 0; mi < 4; mi++)
#pragma unroll
                for (int ni = 0; ni < 4; ni++)
                    mma16816(acc[mi][ni][0], acc[mi][ni][1], acc[mi][ni][2], acc[mi][ni][3],
                             aF[mi][0], aF[mi][1], aF[mi][2], aF[mi][3], bH[ni][0], bH[ni][1]);
        }
        __syncthreads();
    }

    // epilogue: bias + scatter to [d][t][b][h]
#pragma unroll
    for (int ni = 0; ni < 4; ni++) {
        const int n = col0 + (wn << 5) + (ni << 3) + t2;
        const float bs0 = bias1[n] + bias2[n];
        const float bs1 = bias1[n + 1] + bias2[n + 1];
#pragma unroll
        for (int mi = 0; mi < 4; mi++) {
            const int m = row0 + (wm << 6) + (mi << 4) + g;
#pragma unroll
            for (int rr = 0; rr < 2; rr++) {
                const int mm = m + rr * 8;
                int tt, bb;
                if (out_mode == OM_PROJ0) { bb = mm >> 10; tt = mm & 1023; }
                else                      { tt = mm >> 7;  bb = mm & 127;  }
                const size_t base = (((size_t)(n >> 9) * T_ + tt) * B_ + bb) * H_ + (n & 511);
                C[base]     = acc[mi][ni][2 * rr]     + bs0;
                C[base + 1] = acc[mi][ni][2 * rr + 1] + bs1;
            }
        }
    }
}

// ---------------- generic fp32 GEMM (head only) ----------------
__global__ void __launch_bounds__(256) gemm_atb(
    const float* __restrict__ A, int lda,
    const float* __restrict__ W, int ldw,
    const float* __restrict__ bias1, const float* __restrict__ bias2,
    float* __restrict__ C, int M, int N, int K,
    int out_mode, int act)
{
    __shared__ float a_sm[2][16][68];
    __shared__ float w_sm[2][16][68];
    const int tid = threadIdx.x;
    const int row0 = blockIdx.y * 64;
    const int col0 = blockIdx.x * 64;
    const int lm = tid >> 2;
    const int lk = (tid & 3) << 2;

    const float* Ap = A + (size_t)(row0 + lm) * lda + lk;
    const float* Wp = W + (size_t)(col0 + lm) * ldw + lk;
    const int nkt = K >> 4;

    float4 af = *(const float4*)Ap;
    float4 wf = *(const float4*)Wp;
    a_sm[0][lk + 0][lm] = af.x; a_sm[0][lk + 1][lm] = af.y;
    a_sm[0][lk + 2][lm] = af.z; a_sm[0][lk + 3][lm] = af.w;
    w_sm[0][lk + 0][lm] = wf.x; w_sm[0][lk + 1][lm] = wf.y;
    w_sm[0][lk + 2][lm] = wf.z; w_sm[0][lk + 3][lm] = wf.w;
    __syncthreads();

    const int tx = tid & 15, ty = tid >> 4;
    float acc[4][4];
#pragma unroll
    for (int i = 0; i < 4; i++)
#pragma unroll
        for (int j = 0; j < 4; j++) acc[i][j] = 0.f;

    for (int kt = 0; kt < nkt; kt++) {
        const int buf = kt & 1;
        if (kt + 1 < nkt) {
            af = *(const float4*)(Ap + (size_t)(kt + 1) * 16);
            wf = *(const float4*)(Wp + (size_t)(kt + 1) * 16);
        }
#pragma unroll
        for (int k = 0; k < 16; k++) {
            float4 av = *(const float4*)&a_sm[buf][k][ty << 2];
            float4 wv = *(const float4*)&w_sm[buf][k][tx << 2];
            acc[0][0] = fmaf(av.x, wv.x, acc[0][0]);
            acc[0][1] = fmaf(av.x, wv.y, acc[0][1]);
            acc[0][2] = fmaf(av.x, wv.z, acc[0][2]);
            acc[0][3] = fmaf(av.x, wv.w, acc[0][3]);
            acc[1][0] = fmaf(av.y, wv.x, acc[1][0]);
            acc[1][1] = fmaf(av.y, wv.y, acc[1][1]);
            acc[1][2] = fmaf(av.y, wv.z, acc[1][2]);
            acc[1][3] = fmaf(av.y, wv.w, acc[1][3]);
            acc[2][0] = fmaf(av.z, wv.x, acc[2][0]);
            acc[2][1] = fmaf(av.z, wv.y, acc[2][1]);
            acc[2][2] = fmaf(av.z, wv.z, acc[2][2]);
            acc[2][3] = fmaf(av.z, wv.w, acc[2][3]);
            acc[3][0] = fmaf(av.w, wv.x, acc[3][0]);
            acc[3][1] = fmaf(av.w, wv.y, acc[3][1]);
            acc[3][2] = fmaf(av.w, wv.z, acc[3][2]);
            acc[3][3] = fmaf(av.w, wv.w, acc[3][3]);
        }
        if (kt + 1 < nkt) {
            const int nb = buf ^ 1;
            a_sm[nb][lk + 0][lm] = af.x; a_sm[nb][lk + 1][lm] = af.y;
            a_sm[nb][lk + 2][lm] = af.z; a_sm[nb][lk + 3][lm] = af.w;
            w_sm[nb][lk + 0][lm] = wf.x; w_sm[nb][lk + 1][lm] = wf.y;
            w_sm[nb][lk + 2][lm] = wf.z; w_sm[nb][lk + 3][lm] = wf.w;
        }
        __syncthreads();
    }

    float bj[4];
#pragma unroll
    for (int j = 0; j < 4; j++) {
        const int n = col0 + (tx << 2) + j;
        float b = 0.f;
        if (bias1) b += bias1[n];
        if (bias2) b += bias2[n];
        bj[j] = b;
    }
#pragma unroll
    for (int i = 0; i < 4; i++) {
#pragma unroll
        for (int j = 0; j < 4; j++) {
            const int m = row0 + (ty << 2) + i;
            const int n = col0 + (tx << 2) + j;
            float v = acc[i][j] + bj[j];
            if (act == ACT_SIGMOID) v = 1.f / (1.f + expf(-v));
            size_t idx;
            if (out_mode == OM_PLAIN) {
                idx = (size_t)m * N + n;
            } else {
                int tt, bb;
                if (out_mode == OM_PROJ0) { bb = m >> 10; tt = m & 1023; }
                else                      { tt = m >> 7;  bb = m & 127;  }
                idx = (((size_t)(n >> 9) * T_ + tt) * B_ + bb) * H_ + (n & 511);
            }
            C[idx] = v;
        }
    }
}

// ---------------- persistent recurrent scan ----------------
#define SCAN_SMEM ((512 * 32 + 2 * 32 * 64) * 4)   // 81920 B

__global__ void __launch_bounds__(256) scan_kernel(
    const float* __restrict__ proj,   // [2][T][B][H]
    const float* __restrict__ Whh,    // [2][H][H]
    const float* __restrict__ hinit,  // [2][B][H]
    float* __restrict__ S,            // [T][B][2H] or null
    float* __restrict__ outF)         // [B][2H] or null
{
    extern __shared__ float sm[];
    float* wt = sm;                   // [512][32]
    float* ash = sm + 512 * 32;       // [2][32][64]

    const int tid = threadIdx.x;
    const int cta = blockIdx.x;
    const int d = cta >> 6;
    const int rem = cta & 63;
    const int b0 = (rem >> 4) << 5;
    const int n0 = (rem & 15) << 5;

    {
        const int n = tid >> 3;
        const int kq = (tid & 7) << 2;
        const float* wp = Whh + ((size_t)d * H_ + n0 + n) * H_;
        for (int kb = 0; kb < H_; kb += 32) {
            float4 v = *(const float4*)(wp + kb + kq);
            const int k = kb + kq;
            wt[(k + 0) * 32 + n] = v.x;
            wt[(k + 1) * 32 + n] = v.y;
            wt[(k + 2) * 32 + n] = v.z;
            wt[(k + 3) * 32 + n] = v.w;
        }
    }
    for (int i = tid; i < 1024; i += 256) {
        const int m = i >> 5, nn = i & 31;
        g_hbuf[0][d][b0 + m][n0 + nn] = hinit[((size_t)d * B_ + b0 + m) * H_ + n0 + nn];
    }
    gbar(d, 64);

    const int tx = tid & 15, ty = tid >> 4;
    const int m0 = ty << 1;
    const int nn0 = tx << 1;
    const int am = tid >> 3;
    const int ak = (tid & 7) << 3;

    for (int t = 0; t < T_; t++) {
        const float* hp = &g_hbuf[t & 1][d][0][0];
        float* hn = &g_hbuf[(t + 1) & 1][d][0][0];
        const float* pp = proj + (((size_t)d * T_ + t) * B_) * H_;

        const size_t pr0 = (size_t)(b0 + m0) * H_ + n0 + nn0;
        const size_t pr1 = (size_t)(b0 + m0 + 1) * H_ + n0 + nn0;
        const float p00 = pp[pr0], p01 = pp[pr0 + 1];
        const float p10 = pp[pr1], p11 = pp[pr1 + 1];

        const float* arow = hp + (size_t)(b0 + am) * H_ + ak;
        float4 f0 = __ldcg((const float4*)(arow));
        float4 f1 = __ldcg((const float4*)(arow + 4));
        *(float4*)&ash[am * 64 + ak] = f0;
        *(float4*)&ash[am * 64 + ak + 4] = f1;
        __syncthreads();

        float acc00 = 0.f, acc01 = 0.f, acc10 = 0.f, acc11 = 0.f;
        for (int c = 0; c < 8; c++) {
            if (c < 7) {
                f0 = __ldcg((const float4*)(arow + (c + 1) * 64));
                f1 = __ldcg((const float4*)(arow + (c + 1) * 64 + 4));
            }
            const float* ac = ash + (c & 1) * 2048;
            const float* wr = wt + (size_t)(c << 6) * 32;
#pragma unroll
            for (int k = 0; k < 64; k++) {
                const float a0v = ac[m0 * 64 + k];
                const float a1v = ac[(m0 + 1) * 64 + k];
                const float2 wv = *(const float2*)(wr + k * 32 + nn0);
                acc00 = fmaf(a0v, wv.x, acc00);
                acc01 = fmaf(a0v, wv.y, acc01);
                acc10 = fmaf(a1v, wv.x, acc10);
                acc11 = fmaf(a1v, wv.y, acc11);
            }
            if (c < 7) {
                float* ab = ash + ((c + 1) & 1) * 2048;
                *(float4*)&ab[am * 64 + ak] = f0;
                *(float4*)&ab[am * 64 + ak + 4] = f1;
            }
            __syncthreads();
        }

        const float v00 = fmaxf(acc00 + p00, 0.f);
        const float v01 = fmaxf(acc01 + p01, 0.f);
        const float v10 = fmaxf(acc10 + p10, 0.f);
        const float v11 = fmaxf(acc11 + p11, 0.f);

        hn[pr0] = v00; hn[pr0 + 1] = v01;
        hn[pr1] = v10; hn[pr1 + 1] = v11;
        if (S) {
            const size_t s0 = ((size_t)t * B_ + b0 + m0) * (2 * H_) + ((size_t)d << 9) + n0 + nn0;
            S[s0] = v00; S[s0 + 1] = v01;
            S[s0 + 2 * H_] = v10; S[s0 + 2 * H_ + 1] = v11;
        }
        if (outF && t == T_ - 1) {
            const size_t o0 = (size_t)(b0 + m0) * (2 * H_) + ((size_t)d << 9) + n0 + nn0;
            outF[o0] = v00; outF[o0 + 1] = v01;
            outF[o0 + 2 * H_] = v10; outF[o0 + 2 * H_ + 1] = v11;
        }
        gbar(d, 64);
    }
}

// ---------------- BatchNorm(train, biased var) + ReLU ----------------
__global__ void bn_relu(const float* __restrict__ in, float* __restrict__ out,
                        const float* __restrict__ gamma, const float* __restrict__ beta,
                        int Nf)
{
    const int n = blockIdx.x;
    const int t = threadIdx.x;
    const float v = in[(size_t)t * Nf + n];
    __shared__ float red[128];
    red[t] = v;
    __syncthreads();
    for (int s = 64; s > 0; s >>= 1) { if (t < s) red[t] += red[t + s]; __syncthreads(); }
    const float mean = red[0] * (1.f / 128.f);
    __syncthreads();
    const float dv = v - mean;
    red[t] = dv * dv;
    __syncthreads();
    for (int s = 64; s > 0; s >>= 1) { if (t < s) red[t] += red[t + s]; __syncthreads(); }
    const float var = red[0] * (1.f / 128.f);
    const float z = dv * rsqrtf(var + 1e-5f) * gamma[n] + beta[n];
    out[(size_t)t * Nf + n] = fmaxf(z, 0.f);
}

// ---------------- launch ----------------
extern "C" void kernel_launch(void* const* d_in, const int* in_sizes, int n_in,
                              void* d_out, int out_size)
{
    (void)in_sizes; (void)n_in; (void)out_size;
    const float* x     = (const float*)d_in[0];
    const float* h0    = (const float*)d_in[1];
    const float* W_ih0 = (const float*)d_in[2];
    const float* W_hh0 = (const float*)d_in[3];
    const float* b_ih0 = (const float*)d_in[4];
    const float* b_hh0 = (const float*)d_in[5];
    const float* W_ih1 = (const float*)d_in[6];
    const float* W_hh1 = (const float*)d_in[7];
    const float* b_ih1 = (const float*)d_in[8];
    const float* b_hh1 = (const float*)d_in[9];
    const float* bn1_g = (const float*)d_in[10];
    const float* bn1_b = (const float*)d_in[11];
    const float* fc1_W = (const float*)d_in[12];
    const float* fc1_b = (const float*)d_in[13];
    const float* bn2_g = (const float*)d_in[14];
    const float* bn2_b = (const float*)d_in[15];
    const float* fc2_W = (const float*)d_in[16];
    const float* fc2_b = (const float*)d_in[17];
    float* out = (float*)d_out;

    cudaFuncSetAttribute(scan_kernel, cudaFuncAttributeMaxDynamicSharedMemorySize, SCAN_SMEM);

    float *pProj, *pS, *pOut1, *pZ1, *pH1, *pZ2;
    cudaGetSymbolAddress((void**)&pProj, g_proj);
    cudaGetSymbolAddress((void**)&pS, g_S);
    cudaGetSymbolAddress((void**)&pOut1, g_out1);
    cudaGetSymbolAddress((void**)&pZ1, g_z1);
    cudaGetSymbolAddress((void**)&pH1, g_h1);
    cudaGetSymbolAddress((void**)&pZ2, g_z2);

    const int MT = B_ * T_;  // 131072

    // layer0 input projection (tensor cores): [131072,256] x [1024,256]^T
    gemm_tc<<<dim3((2 * H_) / 128, MT / 128), 256>>>(
        x, IN_, W_ih0, IN_, b_ih0, b_hh0, pProj, IN_, OM_PROJ0);

    // layer0 scan
    scan_kernel<<<128, 256, SCAN_SMEM>>>(pProj, W_hh0, h0, pS, nullptr);

    // layer1 input projection (tensor cores): [131072,1024] x [1024,1024]^T
    gemm_tc<<<dim3((2 * H_) / 128, MT / 128), 256>>>(
        pS, 2 * H_, W_ih1, 2 * H_, b_ih1, b_hh1, pProj, 2 * H_, OM_PROJ1);

    // layer1 scan
    scan_kernel<<<128, 256, SCAN_SMEM>>>(pProj, W_hh1, h0 + 2 * B_ * H_, nullptr, pOut1);

    // head (fp32 path)
    bn_relu<<<2 * H_, 128>>>(pOut1, pZ1, bn1_g, bn1_b, 2 * H_);
    gemm_atb<<<dim3((4 * H_) / 64, B_ / 64), 256>>>(
        pZ1, 2 * H_, fc1_W, 2 * H_, fc1_b, nullptr, pH1, B_, 4 * H_, 2 * H_, OM_PLAIN, ACT_NONE);
    bn_relu<<<4 * H_, 128>>>(pH1, pZ2, bn2_g, bn2_b, 4 * H_);
    gemm_atb<<<dim3(128 / 64, B_ / 64), 256>>>(
        pZ2, 4 * H_, fc2_W, 4 * H_, fc2_b, nullptr, out, B_, 128, 4 * H_, OM_PLAIN, ACT_SIGMOID);
}

// round 5
// speedup vs baseline: 1.8534x; 1.5364x over previous
#include <cuda_runtime.h>
#include <cuda_bf16.h>
#include <cstdint>
#include <cstddef>

// Problem constants
#define T_ 1024
#define B_ 128
#define IN_ 256
#define H_ 512

// ---------------- scratch (device globals: allocation-free rule) ----------------
__device__ float g_proj[(size_t)2 * T_ * B_ * H_];   // reused for proj0 then proj1
__device__ float g_S[(size_t)T_ * B_ * (2 * H_)];    // layer0 states [t][b][1024]
__device__ __nv_bfloat16 g_hHi[2][2][B_][H_];        // ping-pong recurrent state (bf16 hi)
__device__ __nv_bfloat16 g_hLo[2][2][B_][H_];        // ping-pong recurrent state (bf16 lo)
__device__ float g_out1[B_ * (2 * H_)];
__device__ float g_z1[B_ * (2 * H_)];
__device__ float g_h1[B_ * (4 * H_)];
__device__ float g_z2[B_ * (4 * H_)];
__device__ unsigned long long g_tick2[8 * 16];       // per-group monotonic tickets (padded)

// ---------------- per-group grid barrier (16 CTAs per group, replay-safe) ----------------
__device__ __forceinline__ void gbar_g(int group) {
    __syncthreads();
    if (threadIdx.x == 0) {
        __threadfence();
        unsigned long long* ctr = &g_tick2[group * 16];
        unsigned long long t = atomicAdd(ctr, 1ULL);
        unsigned long long target = ((t >> 4) + 1ULL) << 4;   // next multiple of 16
        while (__ldcg(ctr) < target) __nanosleep(32);
        __threadfence();
    }
    __syncthreads();
}

#define OM_PLAIN 0
#define OM_PROJ0 1   // row r = b*T + t  (A = x [B,T,IN]) -> out [d][t][b][h]
#define OM_PROJ1 2   // row r = t*B + b  (A = S [T*B,1024]) -> out [d][t][b][h]
#define ACT_NONE 0
#define ACT_SIGMOID 1

__device__ __forceinline__ void mma16816(float& c0, float& c1, float& c2, float& c3,
                                         uint32_t a0, uint32_t a1, uint32_t a2, uint32_t a3,
                                         uint32_t b0, uint32_t b1)
{
    asm volatile(
        "mma.sync.aligned.m16n8k16.row.col.f32.bf16.bf16.f32 "
        "{%0,%1,%2,%3}, {%4,%5,%6,%7}, {%8,%9}, {%0,%1,%2,%3};"
        : "+f"(c0), "+f"(c1), "+f"(c2), "+f"(c3)
        : "r"(a0), "r"(a1), "r"(a2), "r"(a3), "r"(b0), "r"(b1));
}

// ==================================================================================
// Tensor-core GEMM (bf16 split-2, fp32 accumulate): C[m,n] = sum_k A[m,k]*W[n,k]
// ==================================================================================
#define SMSTR 40   // bf16 elements per smem row (32 + 8 pad) -> conflict-free frags

__global__ void __launch_bounds__(256) gemm_tc(
    const float* __restrict__ A, int lda,
    const float* __restrict__ W, int ldw,
    const float* __restrict__ bias1, const float* __restrict__ bias2,
    float* __restrict__ C, int K, int out_mode)
{
    __shared__ __nv_bfloat16 sAh[128 * SMSTR];
    __shared__ __nv_bfloat16 sAl[128 * SMSTR];
    __shared__ __nv_bfloat16 sWh[128 * SMSTR];
    __shared__ __nv_bfloat16 sWl[128 * SMSTR];

    const int tid = threadIdx.x;
    const int row0 = blockIdx.y * 128;
    const int col0 = blockIdx.x * 128;

    const int lrow = tid >> 1;
    const int lcol = (tid & 1) << 4;
    const float* Ap = A + (size_t)(row0 + lrow) * lda + lcol;
    const float* Wp = W + (size_t)(col0 + lrow) * ldw + lcol;

    const int nch = K >> 5;

    float4 apre[4], wpre[4];
#pragma unroll
    for (int j = 0; j < 4; j++) {
        apre[j] = *(const float4*)(Ap + j * 4);
        wpre[j] = *(const float4*)(Wp + j * 4);
    }

    const int warp = tid >> 5;
    const int lane = tid & 31;
    const int wm = warp >> 2;
    const int wn = warp & 3;
    const int g = lane >> 2;
    const int t2 = (lane & 3) << 1;

    float acc[4][4][4];
#pragma unroll
    for (int mi = 0; mi < 4; mi++)
#pragma unroll
        for (int ni = 0; ni < 4; ni++)
#pragma unroll
            for (int r = 0; r < 4; r++) acc[mi][ni][r] = 0.f;

    for (int c = 0; c < nch; c++) {
#pragma unroll
        for (int j = 0; j < 4; j++) {
            float4 v = apre[j];
            __nv_bfloat16 hx = __float2bfloat16(v.x);
            __nv_bfloat16 hy = __float2bfloat16(v.y);
            __nv_bfloat16 hz = __float2bfloat16(v.z);
            __nv_bfloat16 hw = __float2bfloat16(v.w);
            __nv_bfloat16 lx = __float2bfloat16(v.x - __bfloat162float(hx));
            __nv_bfloat16 ly = __float2bfloat16(v.y - __bfloat162float(hy));
            __nv_bfloat16 lz = __float2bfloat16(v.z - __bfloat162float(hz));
            __nv_bfloat16 lw = __float2bfloat16(v.w - __bfloat162float(hw));
            const int o = lrow * SMSTR + lcol + j * 4;
            *(__nv_bfloat162*)&sAh[o]     = __halves2bfloat162(hx, hy);
            *(__nv_bfloat162*)&sAh[o + 2] = __halves2bfloat162(hz, hw);
            *(__nv_bfloat162*)&sAl[o]     = __halves2bfloat162(lx, ly);
            *(__nv_bfloat162*)&sAl[o + 2] = __halves2bfloat162(lz, lw);
            v = wpre[j];
            hx = __float2bfloat16(v.x); hy = __float2bfloat16(v.y);
            hz = __float2bfloat16(v.z); hw = __float2bfloat16(v.w);
            lx = __float2bfloat16(v.x - __bfloat162float(hx));
            ly = __float2bfloat16(v.y - __bfloat162float(hy));
            lz = __float2bfloat16(v.z - __bfloat162float(hz));
            lw = __float2bfloat16(v.w - __bfloat162float(hw));
            *(__nv_bfloat162*)&sWh[o]     = __halves2bfloat162(hx, hy);
            *(__nv_bfloat162*)&sWh[o + 2] = __halves2bfloat162(hz, hw);
            *(__nv_bfloat162*)&sWl[o]     = __halves2bfloat162(lx, ly);
            *(__nv_bfloat162*)&sWl[o + 2] = __halves2bfloat162(lz, lw);
        }
        __syncthreads();

        if (c + 1 < nch) {
#pragma unroll
            for (int j = 0; j < 4; j++) {
                apre[j] = *(const float4*)(Ap + (size_t)(c + 1) * 32 + j * 4);
                wpre[j] = *(const float4*)(Wp + (size_t)(c + 1) * 32 + j * 4);
            }
        }

#pragma unroll
        for (int s = 0; s < 2; s++) {
            const int kb = (s << 4) + t2;
            uint32_t aF[4][4], bH[4][2], bL[4][2];
#pragma unroll
            for (int mi = 0; mi < 4; mi++) {
                const int mb = ((wm << 6) + (mi << 4) + g) * SMSTR + kb;
                aF[mi][0] = *(const uint32_t*)&sAh[mb];
                aF[mi][1] = *(const uint32_t*)&sAh[mb + 8 * SMSTR];
                aF[mi][2] = *(const uint32_t*)&sAh[mb + 8];
                aF[mi][3] = *(const uint32_t*)&sAh[mb + 8 * SMSTR + 8];
            }
#pragma unroll
            for (int ni = 0; ni < 4; ni++) {
                const int nb = ((wn << 5) + (ni << 3) + g) * SMSTR + kb;
                bH[ni][0] = *(const uint32_t*)&sWh[nb];
                bH[ni][1] = *(const uint32_t*)&sWh[nb + 8];
                bL[ni][0] = *(const uint32_t*)&sWl[nb];
                bL[ni][1] = *(const uint32_t*)&sWl[nb + 8];
            }
#pragma unroll
            for (int mi = 0; mi < 4; mi++)
#pragma unroll
                for (int ni = 0; ni < 4; ni++) {
                    mma16816(acc[mi][ni][0], acc[mi][ni][1], acc[mi][ni][2], acc[mi][ni][3],
                             aF[mi][0], aF[mi][1], aF[mi][2], aF[mi][3], bH[ni][0], bH[ni][1]);
                    mma16816(acc[mi][ni][0], acc[mi][ni][1], acc[mi][ni][2], acc[mi][ni][3],
                             aF[mi][0], aF[mi][1], aF[mi][2], aF[mi][3], bL[ni][0], bL[ni][1]);
                }
#pragma unroll
            for (int mi = 0; mi < 4; mi++) {
                const int mb = ((wm << 6) + (mi << 4) + g) * SMSTR + kb;
                aF[mi][0] = *(const uint32_t*)&sAl[mb];
                aF[mi][1] = *(const uint32_t*)&sAl[mb + 8 * SMSTR];
                aF[mi][2] = *(const uint32_t*)&sAl[mb + 8];
                aF[mi][3] = *(const uint32_t*)&sAl[mb + 8 * SMSTR + 8];
            }
#pragma unroll
            for (int mi = 0; mi < 4; mi++)
#pragma unroll
                for (int ni = 0; ni < 4; ni++)
                    mma16816(acc[mi][ni][0], acc[mi][ni][1], acc[mi][ni][2], acc[mi][ni][3],
                             aF[mi][0], aF[mi][1], aF[mi][2], aF[mi][3], bH[ni][0], bH[ni][1]);
        }
        __syncthreads();
    }

#pragma unroll
    for (int ni = 0; ni < 4; ni++) {
        const int n = col0 + (wn << 5) + (ni << 3) + t2;
        const float bs0 = bias1[n] + bias2[n];
        const float bs1 = bias1[n + 1] + bias2[n + 1];
#pragma unroll
        for (int mi = 0; mi < 4; mi++) {
            const int m = row0 + (wm << 6) + (mi << 4) + g;
#pragma unroll
            for (int rr = 0; rr < 2; rr++) {
                const int mm = m + rr * 8;
                int tt, bb;
                if (out_mode == OM_PROJ0) { bb = mm >> 10; tt = mm & 1023; }
                else                      { tt = mm >> 7;  bb = mm & 127;  }
                const size_t base = (((size_t)(n >> 9) * T_ + tt) * B_ + bb) * H_ + (n & 511);
                C[base]     = acc[mi][ni][2 * rr]     + bs0;
                C[base + 1] = acc[mi][ni][2 * rr + 1] + bs1;
            }
        }
    }
}

// ==================================================================================
// Tensor-core persistent recurrent scan.
// 128 CTAs = 2 dir x 4 b-groups x 16 n-tiles; each CTA computes a [32b x 32n] tile
// of h_{t+1} = relu(h_t @ Whh^T + proj_t) with bf16 split-2 MMA.
// Whh hi-fragments live in registers for all 1024 steps; Whh lo + h tiles in smem.
// h state in global as bf16 hi/lo pairs; per-(dir,b-group) barrier (16 CTAs).
// ==================================================================================
#define ASTR 520   // bf16 elems per smem row (512 + 8 pad): frag bank = 4g + t2/2 (perfect)
#define SCANTC_SMEM (4 * 32 * ASTR * 2)   // 133120 B

__global__ void __launch_bounds__(256) scan_tc(
    const float* __restrict__ proj,   // [2][T][B][H] (bias pre-added)
    const float* __restrict__ Whh,    // [2][H][H] fp32
    const float* __restrict__ hinit,  // [2][B][H] fp32
    float* __restrict__ S,            // [T][B][2H] or null
    float* __restrict__ outF)         // [B][2H] or null
{
    extern __shared__ __nv_bfloat16 smc[];
    __nv_bfloat16* aHi = smc;
    __nv_bfloat16* aLo = smc + 32 * ASTR;
    __nv_bfloat16* wHi = smc + 2 * 32 * ASTR;
    __nv_bfloat16* wLo = smc + 3 * 32 * ASTR;

    const int tid = threadIdx.x;
    const int cta = blockIdx.x;
    const int d = cta >> 6;
    const int rem = cta & 63;
    const int bg = rem >> 4;          // 0..3
    const int nt = rem & 15;          // 0..15
    const int b0 = bg << 5;
    const int n0 = nt << 5;
    const int group = (d << 2) + bg;  // 0..7

    // Load + split this CTA's Whh slice [n0..n0+31][0..511] into smem (once).
    for (int idx = tid; idx < 32 * 512; idx += 256) {
        const int n = idx >> 9, k = idx & 511;
        const float w = Whh[((size_t)d * H_ + n0 + n) * H_ + k];
        const __nv_bfloat16 hi = __float2bfloat16(w);
        wHi[n * ASTR + k] = hi;
        wLo[n * ASTR + k] = __float2bfloat16(w - __bfloat162float(hi));
    }
    // Init parity-0 h state for this b-group (one CTA per group does it).
    if (nt == 0) {
        for (int idx = tid; idx < 32 * 512; idx += 256) {
            const int b = idx >> 9, k = idx & 511;
            const float v = hinit[((size_t)d * B_ + b0 + b) * H_ + k];
            const __nv_bfloat16 hi = __float2bfloat16(v);
            g_hHi[0][d][b0 + b][k] = hi;
            g_hLo[0][d][b0 + b][k] = __float2bfloat16(v - __bfloat162float(hi));
        }
    }
    gbar_g(group);   // includes __syncthreads: W smem + h init visible

    const int warp = tid >> 5, lane = tid & 31;
    const int wm = warp >> 2;          // 0..1  -> m offset 0/16
    const int wn = warp & 3;           // 0..3  -> n offset 0/8/16/24
    const int m0 = wm << 4;
    const int nw = wn << 3;
    const int g = lane >> 2;           // 0..7
    const int t2 = (lane & 3) << 1;    // 0,2,4,6

    // Preload Whh-hi B-fragments into registers (constant across all steps).
    uint32_t bh0[32], bh1[32];
    {
        const __nv_bfloat16* wr = wHi + (nw + g) * ASTR + t2;
#pragma unroll
        for (int ks = 0; ks < 32; ks++) {
            bh0[ks] = *(const uint32_t*)(wr + ks * 16);
            bh1[ks] = *(const uint32_t*)(wr + ks * 16 + 8);
        }
    }

    const int sr = tid >> 3;           // staging row 0..31
    const int sj = tid & 7;            // 0..7

    const __nv_bfloat16* am = aHi + (m0 + g) * ASTR + t2;
    const __nv_bfloat16* al = aLo + (m0 + g) * ASTR + t2;
    const __nv_bfloat16* wl = wLo + (nw + g) * ASTR + t2;

    for (int t = 0; t < T_; t++) {
        const int p = t & 1;
        // projection values for this thread's outputs (independent of h)
        const float* pp = proj + (((size_t)d * T_ + t) * B_) * H_;
        const float2 q0 = *(const float2*)(pp + (size_t)(b0 + m0 + g) * H_ + n0 + nw + t2);
        const float2 q1 = *(const float2*)(pp + (size_t)(b0 + m0 + g + 8) * H_ + n0 + nw + t2);

        // stage h tile [32 x 512] hi/lo into smem
        {
            const __nv_bfloat16* srcH = &g_hHi[p][d][b0 + sr][0];
            const __nv_bfloat16* srcL = &g_hLo[p][d][b0 + sr][0];
#pragma unroll
            for (int q = 0; q < 8; q++) {
                const int c8 = (q * 8 + sj) * 8;
                const float4 vh = __ldcg((const float4*)(srcH + c8));
                const float4 vl = __ldcg((const float4*)(srcL + c8));
                *(float4*)&aHi[sr * ASTR + c8] = vh;
                *(float4*)&aLo[sr * ASTR + c8] = vl;
            }
        }
        __syncthreads();

        float c0 = 0.f, c1 = 0.f, c2 = 0.f, c3 = 0.f;
#pragma unroll
        for (int ks = 0; ks < 32; ks++) {
            const int kc = ks * 16;
            const uint32_t a0 = *(const uint32_t*)(am + kc);
            const uint32_t a1 = *(const uint32_t*)(am + kc + 8 * ASTR);
            const uint32_t a2 = *(const uint32_t*)(am + kc + 8);
            const uint32_t a3 = *(const uint32_t*)(am + kc + 8 * ASTR + 8);
            const uint32_t l0 = *(const uint32_t*)(al + kc);
            const uint32_t l1 = *(const uint32_t*)(al + kc + 8 * ASTR);
            const uint32_t l2 = *(const uint32_t*)(al + kc + 8);
            const uint32_t l3 = *(const uint32_t*)(al + kc + 8 * ASTR + 8);
            const uint32_t w0 = *(const uint32_t*)(wl + kc);
            const uint32_t w1 = *(const uint32_t*)(wl + kc + 8);
            mma16816(c0, c1, c2, c3, a0, a1, a2, a3, bh0[ks], bh1[ks]);   // hi*hi
            mma16816(c0, c1, c2, c3, a0, a1, a2, a3, w0, w1);             // hi*lo
            mma16816(c0, c1, c2, c3, l0, l1, l2, l3, bh0[ks], bh1[ks]);   // lo*hi
        }

        // epilogue: relu(acc + proj) -> bf16 hi/lo h state (+ optional S, outF)
        const float v00 = fmaxf(c0 + q0.x, 0.f);
        const float v01 = fmaxf(c1 + q0.y, 0.f);
        const float v10 = fmaxf(c2 + q1.x, 0.f);
        const float v11 = fmaxf(c3 + q1.y, 0.f);

        const int rowA = b0 + m0 + g;
        const int rowB = rowA + 8;
        const int col = n0 + nw + t2;

        const __nv_bfloat16 h00 = __float2bfloat16(v00);
        const __nv_bfloat16 h01 = __float2bfloat16(v01);
        const __nv_bfloat16 h10 = __float2bfloat16(v10);
        const __nv_bfloat16 h11 = __float2bfloat16(v11);
        *(__nv_bfloat162*)&g_hHi[p ^ 1][d][rowA][col] = __halves2bfloat162(h00, h01);
        *(__nv_bfloat162*)&g_hHi[p ^ 1][d][rowB][col] = __halves2bfloat162(h10, h11);
        *(__nv_bfloat162*)&g_hLo[p ^ 1][d][rowA][col] = __halves2bfloat162(
            __float2bfloat16(v00 - __bfloat162float(h00)),
            __float2bfloat16(v01 - __bfloat162float(h01)));
        *(__nv_bfloat162*)&g_hLo[p ^ 1][d][rowB][col] = __halves2bfloat162(
            __float2bfloat16(v10 - __bfloat162float(h10)),
            __float2bfloat16(v11 - __bfloat162float(h11)));

        if (S) {
            const size_t s0 = ((size_t)t * B_ + rowA) * (2 * H_) + ((size_t)d << 9) + col;
            const size_t s1 = ((size_t)t * B_ + rowB) * (2 * H_) + ((size_t)d << 9) + col;
            *(float2*)&S[s0] = make_float2(v00, v01);
            *(float2*)&S[s1] = make_float2(v10, v11);
        }
        if (outF && t == T_ - 1) {
            const size_t o0 = (size_t)rowA * (2 * H_) + ((size_t)d << 9) + col;
            const size_t o1 = (size_t)rowB * (2 * H_) + ((size_t)d << 9) + col;
            *(float2*)&outF[o0] = make_float2(v00, v01);
            *(float2*)&outF[o1] = make_float2(v10, v11);
        }
        gbar_g(group);
    }
}

// ---------------- generic fp32 GEMM (head only) ----------------
__global__ void __launch_bounds__(256) gemm_atb(
    const float* __restrict__ A, int lda,
    const float* __restrict__ W, int ldw,
    const float* __restrict__ bias1, const float* __restrict__ bias2,
    float* __restrict__ C, int M, int N, int K,
    int out_mode, int act)
{
    __shared__ float a_sm[2][16][68];
    __shared__ float w_sm[2][16][68];
    const int tid = threadIdx.x;
    const int row0 = blockIdx.y * 64;
    const int col0 = blockIdx.x * 64;
    const int lm = tid >> 2;
    const int lk = (tid & 3) << 2;

    const float* Ap = A + (size_t)(row0 + lm) * lda + lk;
    const float* Wp = W + (size_t)(col0 + lm) * ldw + lk;
    const int nkt = K >> 4;

    float4 af = *(const float4*)Ap;
    float4 wf = *(const float4*)Wp;
    a_sm[0][lk + 0][lm] = af.x; a_sm[0][lk + 1][lm] = af.y;
    a_sm[0][lk + 2][lm] = af.z; a_sm[0][lk + 3][lm] = af.w;
    w_sm[0][lk + 0][lm] = wf.x; w_sm[0][lk + 1][lm] = wf.y;
    w_sm[0][lk + 2][lm] = wf.z; w_sm[0][lk + 3][lm] = wf.w;
    __syncthreads();

    const int tx = tid & 15, ty = tid >> 4;
    float acc[4][4];
#pragma unroll
    for (int i = 0; i < 4; i++)
#pragma unroll
        for (int j = 0; j < 4; j++) acc[i][j] = 0.f;

    for (int kt = 0; kt < nkt; kt++) {
        const int buf = kt & 1;
        if (kt + 1 < nkt) {
            af = *(const float4*)(Ap + (size_t)(kt + 1) * 16);
            wf = *(const float4*)(Wp + (size_t)(kt + 1) * 16);
        }
#pragma unroll
        for (int k = 0; k < 16; k++) {
            float4 av = *(const float4*)&a_sm[buf][k][ty << 2];
            float4 wv = *(const float4*)&w_sm[buf][k][tx << 2];
            acc[0][0] = fmaf(av.x, wv.x, acc[0][0]);
            acc[0][1] = fmaf(av.x, wv.y, acc[0][1]);
            acc[0][2] = fmaf(av.x, wv.z, acc[0][2]);
            acc[0][3] = fmaf(av.x, wv.w, acc[0][3]);
            acc[1][0] = fmaf(av.y, wv.x, acc[1][0]);
            acc[1][1] = fmaf(av.y, wv.y, acc[1][1]);
            acc[1][2] = fmaf(av.y, wv.z, acc[1][2]);
            acc[1][3] = fmaf(av.y, wv.w, acc[1][3]);
            acc[2][0] = fmaf(av.z, wv.x, acc[2][0]);
            acc[2][1] = fmaf(av.z, wv.y, acc[2][1]);
            acc[2][2] = fmaf(av.z, wv.z, acc[2][2]);
            acc[2][3] = fmaf(av.z, wv.w, acc[2][3]);
            acc[3][0] = fmaf(av.w, wv.x, acc[3][0]);
            acc[3][1] = fmaf(av.w, wv.y, acc[3][1]);
            acc[3][2] = fmaf(av.w, wv.z, acc[3][2]);
            acc[3][3] = fmaf(av.w, wv.w, acc[3][3]);
        }
        if (kt + 1 < nkt) {
            const int nb = buf ^ 1;
            a_sm[nb][lk + 0][lm] = af.x; a_sm[nb][lk + 1][lm] = af.y;
            a_sm[nb][lk + 2][lm] = af.z; a_sm[nb][lk + 3][lm] = af.w;
            w_sm[nb][lk + 0][lm] = wf.x; w_sm[nb][lk + 1][lm] = wf.y;
            w_sm[nb][lk + 2][lm] = wf.z; w_sm[nb][lk + 3][lm] = wf.w;
        }
        __syncthreads();
    }

    float bj[4];
#pragma unroll
    for (int j = 0; j < 4; j++) {
        const int n = col0 + (tx << 2) + j;
        float b = 0.f;
        if (bias1) b += bias1[n];
        if (bias2) b += bias2[n];
        bj[j] = b;
    }
#pragma unroll
    for (int i = 0; i < 4; i++) {
#pragma unroll
        for (int j = 0; j < 4; j++) {
            const int m = row0 + (ty << 2) + i;
            const int n = col0 + (tx << 2) + j;
            float v = acc[i][j] + bj[j];
            if (act == ACT_SIGMOID) v = 1.f / (1.f + expf(-v));
            size_t idx;
            if (out_mode == OM_PLAIN) {
                idx = (size_t)m * N + n;
            } else {
                int tt, bb;
                if (out_mode == OM_PROJ0) { bb = m >> 10; tt = m & 1023; }
                else                      { tt = m >> 7;  bb = m & 127;  }
                idx = (((size_t)(n >> 9) * T_ + tt) * B_ + bb) * H_ + (n & 511);
            }
            C[idx] = v;
        }
    }
}

// ---------------- BatchNorm(train, biased var) + ReLU ----------------
__global__ void bn_relu(const float* __restrict__ in, float* __restrict__ out,
                        const float* __restrict__ gamma, const float* __restrict__ beta,
                        int Nf)
{
    const int n = blockIdx.x;
    const int t = threadIdx.x;
    const float v = in[(size_t)t * Nf + n];
    __shared__ float red[128];
    red[t] = v;
    __syncthreads();
    for (int s = 64; s > 0; s >>= 1) { if (t < s) red[t] += red[t + s]; __syncthreads(); }
    const float mean = red[0] * (1.f / 128.f);
    __syncthreads();
    const float dv = v - mean;
    red[t] = dv * dv;
    __syncthreads();
    for (int s = 64; s > 0; s >>= 1) { if (t < s) red[t] += red[t + s]; __syncthreads(); }
    const float var = red[0] * (1.f / 128.f);
    const float z = dv * rsqrtf(var + 1e-5f) * gamma[n] + beta[n];
    out[(size_t)t * Nf + n] = fmaxf(z, 0.f);
}

// ---------------- launch ----------------
extern "C" void kernel_launch(void* const* d_in, const int* in_sizes, int n_in,
                              void* d_out, int out_size)
{
    (void)in_sizes; (void)n_in; (void)out_size;
    const float* x     = (const float*)d_in[0];
    const float* h0    = (const float*)d_in[1];
    const float* W_ih0 = (const float*)d_in[2];
    const float* W_hh0 = (const float*)d_in[3];
    const float* b_ih0 = (const float*)d_in[4];
    const float* b_hh0 = (const float*)d_in[5];
    const float* W_ih1 = (const float*)d_in[6];
    const float* W_hh1 = (const float*)d_in[7];
    const float* b_ih1 = (const float*)d_in[8];
    const float* b_hh1 = (const float*)d_in[9];
    const float* bn1_g = (const float*)d_in[10];
    const float* bn1_b = (const float*)d_in[11];
    const float* fc1_W = (const float*)d_in[12];
    const float* fc1_b = (const float*)d_in[13];
    const float* bn2_g = (const float*)d_in[14];
    const float* bn2_b = (const float*)d_in[15];
    const float* fc2_W = (const float*)d_in[16];
    const float* fc2_b = (const float*)d_in[17];
    float* out = (float*)d_out;

    cudaFuncSetAttribute(scan_tc, cudaFuncAttributeMaxDynamicSharedMemorySize, SCANTC_SMEM);

    float *pProj, *pS, *pOut1, *pZ1, *pH1, *pZ2;
    cudaGetSymbolAddress((void**)&pProj, g_proj);
    cudaGetSymbolAddress((void**)&pS, g_S);
    cudaGetSymbolAddress((void**)&pOut1, g_out1);
    cudaGetSymbolAddress((void**)&pZ1, g_z1);
    cudaGetSymbolAddress((void**)&pH1, g_h1);
    cudaGetSymbolAddress((void**)&pZ2, g_z2);

    const int MT = B_ * T_;  // 131072

    // layer0 input projection (tensor cores): [131072,256] x [1024,256]^T
    gemm_tc<<<dim3((2 * H_) / 128, MT / 128), 256>>>(
        x, IN_, W_ih0, IN_, b_ih0, b_hh0, pProj, IN_, OM_PROJ0);

    // layer0 scan (tensor cores)
    scan_tc<<<128, 256, SCANTC_SMEM>>>(pProj, W_hh0, h0, pS, nullptr);

    // layer1 input projection (tensor cores): [131072,1024] x [1024,1024]^T
    gemm_tc<<<dim3((2 * H_) / 128, MT / 128), 256>>>(
        pS, 2 * H_, W_ih1, 2 * H_, b_ih1, b_hh1, pProj, 2 * H_, OM_PROJ1);

    // layer1 scan (tensor cores)
    scan_tc<<<128, 256, SCANTC_SMEM>>>(pProj, W_hh1, h0 + 2 * B_ * H_, nullptr, pOut1);

    // head (fp32 path)
    bn_relu<<<2 * H_, 128>>>(pOut1, pZ1, bn1_g, bn1_b, 2 * H_);
    gemm_atb<<<dim3((4 * H_) / 64, B_ / 64), 256>>>(
        pZ1, 2 * H_, fc1_W, 2 * H_, fc1_b, nullptr, pH1, B_, 4 * H_, 2 * H_, OM_PLAIN, ACT_NONE);
    bn_relu<<<4 * H_, 128>>>(pH1, pZ2, bn2_g, bn2_b, 4 * H_);
    gemm_atb<<<dim3(128 / 64, B_ / 64), 256>>>(
        pZ2, 4 * H_, fc2_W, 4 * H_, fc2_b, nullptr, out, B_, 128, 4 * H_, OM_PLAIN, ACT_SIGMOID);
}